// round 14
// baseline (speedup 1.0000x reference)
#include <cuda_runtime.h>
#include <cuda_bf16.h>
#include <cstdint>

#define N_NODES  50000
#define N_PAD    50048          /* 782 tiles * 64 */
#define N_EDGES  800000
#define N_GRAPHS 256
#define HIDDEN   128
#define N_LAYERS 5
#define OUT_DIM  10
#define BN_EPS   1e-5f

// ===================== device scratch (allocation-free) =====================
// agg output stored pre-split as bf16 hi/lo (pad rows stay zero: BSS-init, never written)
__device__ __align__(16) __nv_bfloat16 g_zh[N_PAD * HIDDEN];
__device__ __align__(16) __nv_bfloat16 g_zl[N_PAD * HIDDEN];
__device__ __align__(16) float g_z2[N_PAD * HIDDEN];               // GEMM1 out (pad rows stay 0)
__device__ __align__(16) float g_z3[N_LAYERS][N_NODES * HIDDEN];   // GEMM2 out per layer
__device__ int   g_deg[N_NODES];
__device__ int   g_off[N_NODES + 1];
__device__ int   g_cursor[N_NODES];
__device__ int   g_csr_src[N_EDGES];
__device__ int   g_bsum[256];
__device__ int   g_gstart[N_GRAPHS + 1];
__device__ __align__(16) float g_stat_sum[10][HIDDEN];   // per-GEMM BN stats
__device__ __align__(16) float g_stat_sq [10][HIDDEN];
// W stored transposed [n][k] dense bf16 (128x128), hi and lo parts, 10 slots
#define SLOT_W_BYTES 32768
__device__ __align__(16) unsigned char g_Wh[10 * SLOT_W_BYTES];
__device__ __align__(16) unsigned char g_Wl[10 * SLOT_W_BYTES];

// ===================== mma / ldmatrix wrappers (sm_80+, no arch feature gate) =====================
__device__ __forceinline__ uint32_t smem_u32(const void* p) {
    uint32_t a;
    asm("{ .reg .u64 t; cvta.to.shared.u64 t, %1; cvt.u32.u64 %0, t; }" : "=r"(a) : "l"(p));
    return a;
}
__device__ __forceinline__ void ldmx4(uint32_t* r, uint32_t addr) {
    asm volatile("ldmatrix.sync.aligned.m8n8.x4.shared.b16 {%0,%1,%2,%3}, [%4];"
                 : "=r"(r[0]), "=r"(r[1]), "=r"(r[2]), "=r"(r[3]) : "r"(addr));
}
__device__ __forceinline__ void mma_bf16(float* d, const uint32_t* a, const uint32_t* b) {
    asm volatile("mma.sync.aligned.m16n8k16.row.col.f32.bf16.bf16.f32 "
                 "{%0,%1,%2,%3}, {%4,%5,%6,%7}, {%8,%9}, {%0,%1,%2,%3};"
                 : "+f"(d[0]), "+f"(d[1]), "+f"(d[2]), "+f"(d[3])
                 : "r"(a[0]), "r"(a[1]), "r"(a[2]), "r"(a[3]), "r"(b[0]), "r"(b[1]));
}
__device__ __forceinline__ uint32_t pack_hi(float a, float b) {
    __nv_bfloat16 ha = __float2bfloat16(a), hb = __float2bfloat16(b);
    return (uint32_t)__bfloat16_as_ushort(ha) | ((uint32_t)__bfloat16_as_ushort(hb) << 16);
}
__device__ __forceinline__ uint32_t pack_lo(float a, float b) {
    __nv_bfloat16 ha = __float2bfloat16(a), hb = __float2bfloat16(b);
    __nv_bfloat16 la = __float2bfloat16(a - __bfloat162float(ha));
    __nv_bfloat16 lb = __float2bfloat16(b - __bfloat162float(hb));
    return (uint32_t)__bfloat16_as_ushort(la) | ((uint32_t)__bfloat16_as_ushort(lb) << 16);
}

// ===================== prologue kernels =====================
__global__ void k_zero() {
    int i = blockIdx.x * blockDim.x + threadIdx.x;
    if (i < N_NODES) g_deg[i] = 0;
    if (i < 10 * HIDDEN) {
        ((float*)g_stat_sum)[i] = 0.f;
        ((float*)g_stat_sq)[i]  = 0.f;
    }
}

__global__ void k_hist(const int* __restrict__ ei) {
    int e = blockIdx.x * blockDim.x + threadIdx.x;
    if (e < N_EDGES) atomicAdd(&g_deg[ei[N_EDGES + e]], 1);
}

__global__ void k_scan1() {
    __shared__ int sh[256];
    int b = blockIdx.x, t = threadIdx.x, i = b * 256 + t;
    int v = (i < N_NODES) ? g_deg[i] : 0;
    sh[t] = v; __syncthreads();
    #pragma unroll
    for (int off = 1; off < 256; off <<= 1) {
        int a = (t >= off) ? sh[t - off] : 0; __syncthreads();
        sh[t] += a; __syncthreads();
    }
    if (i < N_NODES) g_off[i + 1] = sh[t];
    if (t == 255) g_bsum[b] = sh[255];
}

// fused: block-sum scan (each block re-scans locally) + offset fixup + cursor + gstart
__global__ void k_scan23g(const int* __restrict__ batch) {
    __shared__ int sh[256];
    int b = blockIdx.x, t = threadIdx.x, i = b * 256 + t;
    int v = (t < 196) ? g_bsum[t] : 0;
    sh[t] = v; __syncthreads();
    #pragma unroll
    for (int off = 1; off < 256; off <<= 1) {
        int a = (t >= off) ? sh[t - off] : 0; __syncthreads();
        sh[t] += a; __syncthreads();
    }
    int pref = (b == 0) ? 0 : sh[b - 1];
    if (i < N_NODES) {
        int o = g_off[i + 1] + pref;
        g_off[i + 1] = o;
        g_cursor[i]  = o - g_deg[i];
        // gstart (batch is sorted)
        int bb = batch[i];
        int bp = (i == 0) ? -1 : batch[i - 1];
        for (int g = bp + 1; g <= bb; g++) g_gstart[g] = i;
        if (i == N_NODES - 1)
            for (int g = bb + 1; g <= N_GRAPHS; g++) g_gstart[g] = N_NODES;
    }
    if (b == 0 && t == 0) g_off[0] = 0;
}

__global__ void k_scatter(const int* __restrict__ ei) {
    int e = blockIdx.x * blockDim.x + threadIdx.x;
    if (e < N_EDGES) {
        int d = ei[N_EDGES + e];
        int p = atomicAdd(&g_cursor[d], 1);
        g_csr_src[p] = ei[e];
    }
}

// W[k][n] fp32 -> transposed dense bf16 [n][k] hi/lo (split: w = hi + lo)
__global__ void k_convW(const float* __restrict__ W1, const float* __restrict__ W2) {
    int slot = blockIdx.x;  // 0..9 : layer*2 + which
    const float* src = (slot & 1) ? (W2 + (slot >> 1) * 16384)
                                  : (W1 + (slot >> 1) * 16384);
    __nv_bfloat16* dh = (__nv_bfloat16*)(g_Wh + slot * SLOT_W_BYTES);
    __nv_bfloat16* dl = (__nv_bfloat16*)(g_Wl + slot * SLOT_W_BYTES);
    for (int e = threadIdx.x; e < 16384; e += 256) {
        int k = e >> 7, n = e & 127;
        float w = src[e];
        __nv_bfloat16 h = __float2bfloat16(w);
        __nv_bfloat16 l = __float2bfloat16(w - __bfloat162float(h));
        dh[n * 128 + k] = h;
        dl[n * 128 + k] = l;
    }
}

// ===================== neighbor aggregation (warp per node, float4 lanes) =====================
// z[v] = f(src[v]) + sum_{u->v} f(src[u]),  f = identity (FIRST) or relu(a*x+b) (BN2 of prev layer)
// Output: bf16 hi/lo split written directly (consumed by GEMM1 staging as raw copies).
template <bool FIRST>
__global__ __launch_bounds__(256) void k_agg(const float* __restrict__ xin,
                                             const float* __restrict__ gamma,
                                             const float* __restrict__ beta,
                                             int slot, int zprev) {
    __shared__ float s_a[HIDDEN], s_b[HIDDEN];
    int t = threadIdx.x, lane = t & 31;
    if (!FIRST) {
        if (t < HIDDEN) {
            const float invN = 1.f / (float)N_NODES;
            float m = g_stat_sum[slot][t] * invN;
            float v = g_stat_sq[slot][t] * invN - m * m;
            float a = gamma[t] * rsqrtf(v + BN_EPS);
            s_a[t] = a;
            s_b[t] = beta[t] - m * a;
        }
        __syncthreads();
    }
    int node = blockIdx.x * 8 + (t >> 5);           // grid 6250 * 8 warps = 50000
    const float4* src = FIRST ? (const float4*)xin : (const float4*)g_z3[zprev];
    float4 av, bv;
    if (!FIRST) { av = ((const float4*)s_a)[lane]; bv = ((const float4*)s_b)[lane]; }

    int beg = g_off[node], end = g_off[node + 1];
    float4 acc = src[node * 32 + lane];
    if (!FIRST) {
        acc.x = fmaxf(fmaf(acc.x, av.x, bv.x), 0.f);
        acc.y = fmaxf(fmaf(acc.y, av.y, bv.y), 0.f);
        acc.z = fmaxf(fmaf(acc.z, av.z, bv.z), 0.f);
        acc.w = fmaxf(fmaf(acc.w, av.w, bv.w), 0.f);
    }
    int j = beg;
    for (; j + 4 <= end; j += 4) {
        int n0 = g_csr_src[j],     n1 = g_csr_src[j + 1];
        int n2 = g_csr_src[j + 2], n3 = g_csr_src[j + 3];
        float4 v0 = src[n0 * 32 + lane];
        float4 v1 = src[n1 * 32 + lane];
        float4 v2 = src[n2 * 32 + lane];
        float4 v3 = src[n3 * 32 + lane];
        if (!FIRST) {
            v0.x = fmaxf(fmaf(v0.x, av.x, bv.x), 0.f); v0.y = fmaxf(fmaf(v0.y, av.y, bv.y), 0.f);
            v0.z = fmaxf(fmaf(v0.z, av.z, bv.z), 0.f); v0.w = fmaxf(fmaf(v0.w, av.w, bv.w), 0.f);
            v1.x = fmaxf(fmaf(v1.x, av.x, bv.x), 0.f); v1.y = fmaxf(fmaf(v1.y, av.y, bv.y), 0.f);
            v1.z = fmaxf(fmaf(v1.z, av.z, bv.z), 0.f); v1.w = fmaxf(fmaf(v1.w, av.w, bv.w), 0.f);
            v2.x = fmaxf(fmaf(v2.x, av.x, bv.x), 0.f); v2.y = fmaxf(fmaf(v2.y, av.y, bv.y), 0.f);
            v2.z = fmaxf(fmaf(v2.z, av.z, bv.z), 0.f); v2.w = fmaxf(fmaf(v2.w, av.w, bv.w), 0.f);
            v3.x = fmaxf(fmaf(v3.x, av.x, bv.x), 0.f); v3.y = fmaxf(fmaf(v3.y, av.y, bv.y), 0.f);
            v3.z = fmaxf(fmaf(v3.z, av.z, bv.z), 0.f); v3.w = fmaxf(fmaf(v3.w, av.w, bv.w), 0.f);
        }
        acc.x += v0.x + v1.x + v2.x + v3.x;
        acc.y += v0.y + v1.y + v2.y + v3.y;
        acc.z += v0.z + v1.z + v2.z + v3.z;
        acc.w += v0.w + v1.w + v2.w + v3.w;
    }
    for (; j < end; j++) {
        float4 v = src[g_csr_src[j] * 32 + lane];
        if (!FIRST) {
            v.x = fmaxf(fmaf(v.x, av.x, bv.x), 0.f);
            v.y = fmaxf(fmaf(v.y, av.y, bv.y), 0.f);
            v.z = fmaxf(fmaf(v.z, av.z, bv.z), 0.f);
            v.w = fmaxf(fmaf(v.w, av.w, bv.w), 0.f);
        }
        acc.x += v.x; acc.y += v.y; acc.z += v.z; acc.w += v.w;
    }
    // write bf16 hi/lo split (4 channels = one uint2 per array)
    uint2 hv = make_uint2(pack_hi(acc.x, acc.y), pack_hi(acc.z, acc.w));
    uint2 lv = make_uint2(pack_lo(acc.x, acc.y), pack_lo(acc.z, acc.w));
    ((uint2*)g_zh)[node * 32 + lane] = hv;
    ((uint2*)g_zl)[node * 32 + lane] = lv;
}

// ===================== HMMA GEMM: 64-row tiles, [N_PAD x128]@[128x128]+bias, bf16 split x3 =====================
// TRANS=false: A = g_zh/g_zl (pre-split bf16)            -> out=g_z2,       stats slot=wslot
// TRANS=true : A = g_z2 with fused relu(BN1(x)) + split  -> out=g_z3[zidx], stats slot=wslot
// Grid = 782 (64-row tiles); smem 107 KB -> 2 CTAs/SM.
#define LDA 272
#define SM_AH   0          /* 64*272  = 17408 */
#define SM_AL   17408
#define SM_WH   34816      /* 128*272 = 34816 */
#define SM_WL   69632
#define SM_BIAS 104448
#define SM_SUM  104960
#define SM_SQ   105472
#define SM_A1   105984
#define SM_B1   106496
#define SM_TOTAL 107008

template <bool TRANS>
__global__ __launch_bounds__(256, 2) void k_gemm_mma(int wslot, const float* __restrict__ bias,
                                                     const float* __restrict__ gamma,
                                                     const float* __restrict__ beta,
                                                     int zidx) {
    extern __shared__ __align__(16) char smem[];
    uint32_t sb = smem_u32(smem);
    int t = threadIdx.x, lane = t & 31, wid = t >> 5;
    int wm = wid & 1, wn = wid >> 1;           // 2 x 4 warp grid: 32-row x 32-col per warp
    int m0 = blockIdx.x * 64;
    float* out = TRANS ? g_z3[zidx] : g_z2;

    float* s_bias = (float*)(smem + SM_BIAS);
    float* s_sum  = (float*)(smem + SM_SUM);
    float* s_sq   = (float*)(smem + SM_SQ);
    float* s_a1   = (float*)(smem + SM_A1);
    float* s_b1   = (float*)(smem + SM_B1);
    if (t < 128) {
        s_bias[t] = bias[t]; s_sum[t] = 0.f; s_sq[t] = 0.f;
        if (TRANS) {
            const float invN = 1.f / (float)N_NODES;
            float m = g_stat_sum[wslot - 1][t] * invN;
            float v = g_stat_sq[wslot - 1][t] * invN - m * m;
            float a = gamma[t] * rsqrtf(v + BN_EPS);
            s_a1[t] = a;
            s_b1[t] = beta[t] - m * a;
        }
    }
    // ---- stage W (hi/lo), padded rows ----
    {
        const float4* wh = (const float4*)(g_Wh + wslot * SLOT_W_BYTES);
        const float4* wl = (const float4*)(g_Wl + wslot * SLOT_W_BYTES);
        #pragma unroll
        for (int i = t; i < 2048; i += 256) {
            int row = i >> 4, c8 = i & 15;
            *(float4*)(smem + SM_WH + row * LDA + c8 * 16) = wh[i];
            *(float4*)(smem + SM_WL + row * LDA + c8 * 16) = wl[i];
        }
    }
    // ---- stage A tile (64 rows) ----
    if (TRANS) {
        __syncthreads();   // s_a1/s_b1 ready
        #pragma unroll
        for (int i = t; i < 2048; i += 256) {
            int row = i >> 5, c4 = i & 31;
            float4 v = ((const float4*)g_z2)[(m0 + row) * 32 + c4];
            float4 al = ((const float4*)s_a1)[c4];
            float4 be = ((const float4*)s_b1)[c4];
            v.x = fmaxf(fmaf(v.x, al.x, be.x), 0.f);
            v.y = fmaxf(fmaf(v.y, al.y, be.y), 0.f);
            v.z = fmaxf(fmaf(v.z, al.z, be.z), 0.f);
            v.w = fmaxf(fmaf(v.w, al.w, be.w), 0.f);
            uint2 hv = make_uint2(pack_hi(v.x, v.y), pack_hi(v.z, v.w));
            uint2 lv = make_uint2(pack_lo(v.x, v.y), pack_lo(v.z, v.w));
            *(uint2*)(smem + SM_AH + row * LDA + c4 * 8) = hv;
            *(uint2*)(smem + SM_AL + row * LDA + c4 * 8) = lv;
        }
    } else {
        #pragma unroll
        for (int i = t; i < 1024; i += 256) {
            int row = i >> 4, c16 = i & 15;   // 16B chunks: 128 bf16 = 256B = 16 chunks
            float4 hv = ((const float4*)g_zh)[(m0 + row) * 16 + c16];
            float4 lv = ((const float4*)g_zl)[(m0 + row) * 16 + c16];
            *(float4*)(smem + SM_AH + row * LDA + c16 * 16) = hv;
            *(float4*)(smem + SM_AL + row * LDA + c16 * 16) = lv;
        }
    }
    __syncthreads();

    // fragment addresses
    uint32_t aoffH = sb + SM_AH + (32 * wm + (lane & 15)) * LDA + (lane >> 4) * 16;
    uint32_t aoffL = aoffH + (SM_AL - SM_AH);
    int bg = lane >> 3;
    uint32_t boffH = sb + SM_WH + (32 * wn + (lane & 7) + ((bg >> 1) << 3)) * LDA + (bg & 1) * 16;
    uint32_t boffL = boffH + (SM_WL - SM_WH);

    float acc[2][4][4];
    #pragma unroll
    for (int mt = 0; mt < 2; mt++)
        #pragma unroll
        for (int nt = 0; nt < 4; nt++)
            #pragma unroll
            for (int j = 0; j < 4; j++) acc[mt][nt][j] = 0.f;

    #pragma unroll
    for (int ks = 0; ks < 8; ks++) {
        uint32_t kb = ks * 32;
        uint32_t ah[2][4], al[2][4], bh[2][4], bl[2][4];
        #pragma unroll
        for (int mt = 0; mt < 2; mt++) {
            ldmx4(ah[mt], aoffH + mt * 16 * LDA + kb);
            ldmx4(al[mt], aoffL + mt * 16 * LDA + kb);
        }
        #pragma unroll
        for (int p = 0; p < 2; p++) {
            ldmx4(bh[p], boffH + p * 16 * LDA + kb);
            ldmx4(bl[p], boffL + p * 16 * LDA + kb);
        }
        #pragma unroll
        for (int mt = 0; mt < 2; mt++)
            #pragma unroll
            for (int nt = 0; nt < 4; nt++) {
                const uint32_t* bfh = &bh[nt >> 1][(nt & 1) * 2];
                const uint32_t* bfl = &bl[nt >> 1][(nt & 1) * 2];
                mma_bf16(acc[mt][nt], ah[mt], bfh);   // Ah * Wh
                mma_bf16(acc[mt][nt], al[mt], bfh);   // Al * Wh
                mma_bf16(acc[mt][nt], ah[mt], bfl);   // Ah * Wl
            }
    }

    // ---- epilogue: bias, guarded store, BN stats ----
    int colbase = 32 * wn + 2 * (lane & 3);
    int rowg    = m0 + 32 * wm + (lane >> 2);
    #pragma unroll
    for (int nt = 0; nt < 4; nt++) {
        int c = colbase + nt * 8;
        float b0 = s_bias[c], b1 = s_bias[c + 1];
        float s0 = 0.f, s1 = 0.f, q0 = 0.f, q1 = 0.f;
        #pragma unroll
        for (int mt = 0; mt < 2; mt++) {
            int r0 = rowg + mt * 16;
            int r1 = r0 + 8;
            float d0 = acc[mt][nt][0] + b0, d1 = acc[mt][nt][1] + b1;
            float d2 = acc[mt][nt][2] + b0, d3 = acc[mt][nt][3] + b1;
            if (r0 < N_NODES) {
                *(float2*)(out + r0 * 128 + c) = make_float2(d0, d1);
                s0 += d0; s1 += d1;
                q0 = fmaf(d0, d0, q0); q1 = fmaf(d1, d1, q1);
            }
            if (r1 < N_NODES) {
                *(float2*)(out + r1 * 128 + c) = make_float2(d2, d3);
                s0 += d2; s1 += d3;
                q0 = fmaf(d2, d2, q0); q1 = fmaf(d3, d3, q1);
            }
        }
        #pragma unroll
        for (int off = 4; off < 32; off <<= 1) {
            s0 += __shfl_xor_sync(0xffffffffu, s0, off);
            s1 += __shfl_xor_sync(0xffffffffu, s1, off);
            q0 += __shfl_xor_sync(0xffffffffu, q0, off);
            q1 += __shfl_xor_sync(0xffffffffu, q1, off);
        }
        if (lane < 4) {
            atomicAdd(&s_sum[c], s0);
            atomicAdd(&s_sum[c + 1], s1);
            atomicAdd(&s_sq[c], q0);
            atomicAdd(&s_sq[c + 1], q1);
        }
    }
    __syncthreads();
    if (t < 128)  atomicAdd(&g_stat_sum[wslot][t], s_sum[t]);
    else          atomicAdd(&g_stat_sq[wslot][t - 128], s_sq[t - 128]);
}

// ===================== final MLP with fused 5-layer pooling =====================
// 512 threads: q = t>>7 handles a quarter of the graph's nodes, c = t&127 the channel.
__global__ __launch_bounds__(512) void k_fc(const float* __restrict__ obg,
                                            const float* __restrict__ obb,
                                            const float* __restrict__ fc1W,
                                            const float* __restrict__ fc1b,
                                            const float* __restrict__ fc2W,
                                            const float* __restrict__ fc2b,
                                            float* __restrict__ out) {
    __shared__ float part[4][N_LAYERS * HIDDEN];
    __shared__ float p[N_LAYERS * HIDDEN];
    __shared__ float f1[HIDDEN];
    int g = blockIdx.x, t = threadIdx.x;
    int c = t & 127, q = t >> 7;
    const float invN = 1.f / (float)N_NODES;

    // BN2 affine per layer (all q redundantly compute — cheap)
    float aa[N_LAYERS], bb[N_LAYERS];
    #pragma unroll
    for (int l = 0; l < N_LAYERS; l++) {
        int slot = 2 * l + 1;
        float m = g_stat_sum[slot][c] * invN;
        float v = g_stat_sq[slot][c] * invN - m * m;
        float a = obg[l * HIDDEN + c] * rsqrtf(v + BN_EPS);
        aa[l] = a;
        bb[l] = obb[l * HIDDEN + c] - m * a;
    }

    int beg = g_gstart[g], end = g_gstart[g + 1];
    int len = end - beg;
    int s = beg + (len * q) / 4;
    int e = beg + (len * (q + 1)) / 4;
    float acc[N_LAYERS];
    #pragma unroll
    for (int l = 0; l < N_LAYERS; l++) acc[l] = 0.f;
    for (int i = s; i < e; i++) {
        #pragma unroll
        for (int l = 0; l < N_LAYERS; l++)
            acc[l] += fmaxf(fmaf(g_z3[l][i * HIDDEN + c], aa[l], bb[l]), 0.f);
    }
    #pragma unroll
    for (int l = 0; l < N_LAYERS; l++) part[q][l * HIDDEN + c] = acc[l];
    __syncthreads();
    for (int j = t; j < N_LAYERS * HIDDEN; j += 512)
        p[j] = part[0][j] + part[1][j] + part[2][j] + part[3][j];
    __syncthreads();

    if (q == 0) {
        float sacc = fc1b[c];
        for (int k = 0; k < N_LAYERS * HIDDEN; k++)
            sacc = fmaf(p[k], fc1W[k * HIDDEN + c], sacc);
        f1[c] = fmaxf(sacc, 0.f);
    }
    __syncthreads();
    if (t < OUT_DIM) {
        float o = fc2b[t];
        for (int k = 0; k < HIDDEN; k++)
            o = fmaf(f1[k], fc2W[k * OUT_DIM + t], o);
        out[g * OUT_DIM + t] = o;
    }
}

// ===================== host launch =====================
extern "C" void kernel_launch(void* const* d_in, const int* in_sizes, int n_in,
                              void* d_out, int out_size) {
    const float* x        = (const float*)d_in[0];
    const float* conv_W1  = (const float*)d_in[1];
    const float* conv_b1  = (const float*)d_in[2];
    const float* mlp_bn_g = (const float*)d_in[3];
    const float* mlp_bn_b = (const float*)d_in[4];
    const float* conv_W2  = (const float*)d_in[5];
    const float* conv_b2  = (const float*)d_in[6];
    const float* out_bn_g = (const float*)d_in[7];
    const float* out_bn_b = (const float*)d_in[8];
    const float* fc1_W    = (const float*)d_in[9];
    const float* fc1_b    = (const float*)d_in[10];
    const float* fc2_W    = (const float*)d_in[11];
    const float* fc2_b    = (const float*)d_in[12];
    const int*   ei       = (const int*)  d_in[13];
    const int*   batch    = (const int*)  d_in[14];
    float* out = (float*)d_out;

    cudaFuncSetAttribute((const void*)k_gemm_mma<false>,
                         cudaFuncAttributeMaxDynamicSharedMemorySize, SM_TOTAL);
    cudaFuncSetAttribute((const void*)k_gemm_mma<true>,
                         cudaFuncAttributeMaxDynamicSharedMemorySize, SM_TOTAL);

    k_zero<<<196, 256>>>();
    k_hist<<<(N_EDGES + 255) / 256, 256>>>(ei);
    k_scan1<<<196, 256>>>();
    k_scan23g<<<196, 256>>>(batch);
    k_scatter<<<(N_EDGES + 255) / 256, 256>>>(ei);
    k_convW<<<10, 256>>>(conv_W1, conv_W2);

    const int GB = N_PAD / 64;    // 782 (64-row tiles)
    const int AB = N_NODES / 8;   // 6250 (exact)
    for (int i = 0; i < N_LAYERS; i++) {
        if (i == 0)
            k_agg<true><<<AB, 256>>>(x, nullptr, nullptr, 0, 0);
        else
            k_agg<false><<<AB, 256>>>(nullptr, out_bn_g + (i - 1) * HIDDEN,
                                      out_bn_b + (i - 1) * HIDDEN, 2 * (i - 1) + 1, i - 1);
        k_gemm_mma<false><<<GB, 256, SM_TOTAL>>>(2 * i, conv_b1 + i * HIDDEN,
                                                 nullptr, nullptr, 0);
        k_gemm_mma<true><<<GB, 256, SM_TOTAL>>>(2 * i + 1, conv_b2 + i * HIDDEN,
                                                mlp_bn_g + i * HIDDEN, mlp_bn_b + i * HIDDEN, i);
    }
    k_fc<<<N_GRAPHS, 512>>>(out_bn_g, out_bn_b, fc1_W, fc1_b, fc2_W, fc2_b, out);
}

// round 15
// speedup vs baseline: 1.1275x; 1.1275x over previous
#include <cuda_runtime.h>
#include <cuda_bf16.h>
#include <cstdint>

#define N_NODES  50000
#define N_PAD    50048          /* 782 tiles * 64 */
#define N_EDGES  800000
#define N_GRAPHS 256
#define HIDDEN   128
#define N_LAYERS 5
#define OUT_DIM  10
#define BN_EPS   1e-5f
#define N_TILES  (N_PAD / 64)   /* 782 */
#define GEMM_GRID 304           /* 2 CTAs/SM x 152 SMs, persistent */

// ===================== device scratch (allocation-free) =====================
// agg output stored pre-split as bf16 hi/lo (pad rows stay zero: BSS-init, never written)
__device__ __align__(16) __nv_bfloat16 g_zh[N_PAD * HIDDEN];
__device__ __align__(16) __nv_bfloat16 g_zl[N_PAD * HIDDEN];
__device__ __align__(16) float g_z2[N_PAD * HIDDEN];     // GEMM1 out (pad rows stay 0)
__device__ __align__(16) float g_z3[N_NODES * HIDDEN];   // GEMM2 out (pre-BN2 z)
__device__ int   g_deg[N_NODES];
__device__ int   g_off[N_NODES + 1];
__device__ int   g_cursor[N_NODES];
__device__ int   g_csr_src[N_EDGES];
__device__ int   g_bsum[256];
__device__ int   g_gstart[N_GRAPHS + 1];
__device__ __align__(16) float g_stat_sum[10][HIDDEN];   // per-GEMM BN stats
__device__ __align__(16) float g_stat_sq [10][HIDDEN];
__device__ __align__(16) float g_pooled[N_GRAPHS * N_LAYERS * HIDDEN];
// W stored transposed [n][k] dense bf16 (128x128), hi and lo parts, 10 slots
#define SLOT_W_BYTES 32768
__device__ __align__(16) unsigned char g_Wh[10 * SLOT_W_BYTES];
__device__ __align__(16) unsigned char g_Wl[10 * SLOT_W_BYTES];

// ===================== mma / ldmatrix wrappers (sm_80+, no arch feature gate) =====================
__device__ __forceinline__ uint32_t smem_u32(const void* p) {
    uint32_t a;
    asm("{ .reg .u64 t; cvta.to.shared.u64 t, %1; cvt.u32.u64 %0, t; }" : "=r"(a) : "l"(p));
    return a;
}
__device__ __forceinline__ void ldmx4(uint32_t* r, uint32_t addr) {
    asm volatile("ldmatrix.sync.aligned.m8n8.x4.shared.b16 {%0,%1,%2,%3}, [%4];"
                 : "=r"(r[0]), "=r"(r[1]), "=r"(r[2]), "=r"(r[3]) : "r"(addr));
}
__device__ __forceinline__ void mma_bf16(float* d, const uint32_t* a, const uint32_t* b) {
    asm volatile("mma.sync.aligned.m16n8k16.row.col.f32.bf16.bf16.f32 "
                 "{%0,%1,%2,%3}, {%4,%5,%6,%7}, {%8,%9}, {%0,%1,%2,%3};"
                 : "+f"(d[0]), "+f"(d[1]), "+f"(d[2]), "+f"(d[3])
                 : "r"(a[0]), "r"(a[1]), "r"(a[2]), "r"(a[3]), "r"(b[0]), "r"(b[1]));
}
__device__ __forceinline__ uint32_t pack_hi(float a, float b) {
    __nv_bfloat16 ha = __float2bfloat16(a), hb = __float2bfloat16(b);
    return (uint32_t)__bfloat16_as_ushort(ha) | ((uint32_t)__bfloat16_as_ushort(hb) << 16);
}
__device__ __forceinline__ uint32_t pack_lo(float a, float b) {
    __nv_bfloat16 ha = __float2bfloat16(a), hb = __float2bfloat16(b);
    __nv_bfloat16 la = __float2bfloat16(a - __bfloat162float(ha));
    __nv_bfloat16 lb = __float2bfloat16(b - __bfloat162float(hb));
    return (uint32_t)__bfloat16_as_ushort(la) | ((uint32_t)__bfloat16_as_ushort(lb) << 16);
}

// ===================== prologue kernels =====================
__global__ void k_zero() {
    int i = blockIdx.x * blockDim.x + threadIdx.x;
    if (i < N_NODES) g_deg[i] = 0;
    if (i < 10 * HIDDEN) {
        ((float*)g_stat_sum)[i] = 0.f;
        ((float*)g_stat_sq)[i]  = 0.f;
    }
    if (i < N_GRAPHS * N_LAYERS * HIDDEN) g_pooled[i] = 0.f;
}

__global__ void k_hist(const int* __restrict__ ei) {
    int e = blockIdx.x * blockDim.x + threadIdx.x;
    if (e < N_EDGES) atomicAdd(&g_deg[ei[N_EDGES + e]], 1);
}

__global__ void k_scan1() {
    __shared__ int sh[256];
    int b = blockIdx.x, t = threadIdx.x, i = b * 256 + t;
    int v = (i < N_NODES) ? g_deg[i] : 0;
    sh[t] = v; __syncthreads();
    #pragma unroll
    for (int off = 1; off < 256; off <<= 1) {
        int a = (t >= off) ? sh[t - off] : 0; __syncthreads();
        sh[t] += a; __syncthreads();
    }
    if (i < N_NODES) g_off[i + 1] = sh[t];
    if (t == 255) g_bsum[b] = sh[255];
}

// fused: block-sum scan (each block re-scans locally) + offset fixup + cursor + gstart
__global__ void k_scan23g(const int* __restrict__ batch) {
    __shared__ int sh[256];
    int b = blockIdx.x, t = threadIdx.x, i = b * 256 + t;
    int v = (t < 196) ? g_bsum[t] : 0;
    sh[t] = v; __syncthreads();
    #pragma unroll
    for (int off = 1; off < 256; off <<= 1) {
        int a = (t >= off) ? sh[t - off] : 0; __syncthreads();
        sh[t] += a; __syncthreads();
    }
    int pref = (b == 0) ? 0 : sh[b - 1];
    if (i < N_NODES) {
        int o = g_off[i + 1] + pref;
        g_off[i + 1] = o;
        g_cursor[i]  = o - g_deg[i];
        int bb = batch[i];
        int bp = (i == 0) ? -1 : batch[i - 1];
        for (int g = bp + 1; g <= bb; g++) g_gstart[g] = i;
        if (i == N_NODES - 1)
            for (int g = bb + 1; g <= N_GRAPHS; g++) g_gstart[g] = N_NODES;
    }
    if (b == 0 && t == 0) g_off[0] = 0;
}

__global__ void k_scatter(const int* __restrict__ ei) {
    int e = blockIdx.x * blockDim.x + threadIdx.x;
    if (e < N_EDGES) {
        int d = ei[N_EDGES + e];
        int p = atomicAdd(&g_cursor[d], 1);
        g_csr_src[p] = ei[e];
    }
}

// W[k][n] fp32 -> transposed dense bf16 [n][k] hi/lo (split: w = hi + lo)
__global__ void k_convW(const float* __restrict__ W1, const float* __restrict__ W2) {
    int slot = blockIdx.x;  // 0..9 : layer*2 + which
    const float* src = (slot & 1) ? (W2 + (slot >> 1) * 16384)
                                  : (W1 + (slot >> 1) * 16384);
    __nv_bfloat16* dh = (__nv_bfloat16*)(g_Wh + slot * SLOT_W_BYTES);
    __nv_bfloat16* dl = (__nv_bfloat16*)(g_Wl + slot * SLOT_W_BYTES);
    for (int e = threadIdx.x; e < 16384; e += 256) {
        int k = e >> 7, n = e & 127;
        float w = src[e];
        __nv_bfloat16 h = __float2bfloat16(w);
        __nv_bfloat16 l = __float2bfloat16(w - __bfloat162float(h));
        dh[n * 128 + k] = h;
        dl[n * 128 + k] = l;
    }
}

// ===================== neighbor aggregation (warp per node, float4 lanes) =====================
// z[v] = f(src[v]) + sum_{u->v} f(src[u]),  f = identity (FIRST) or relu(a*x+b) (BN2 of prev layer)
// Output: bf16 hi/lo split written directly (consumed by GEMM1 staging as raw copies).
template <bool FIRST>
__global__ __launch_bounds__(256) void k_agg(const float* __restrict__ xin,
                                             const float* __restrict__ gamma,
                                             const float* __restrict__ beta,
                                             int slot) {
    __shared__ float s_a[HIDDEN], s_b[HIDDEN];
    int t = threadIdx.x, lane = t & 31;
    if (!FIRST) {
        if (t < HIDDEN) {
            const float invN = 1.f / (float)N_NODES;
            float m = g_stat_sum[slot][t] * invN;
            float v = g_stat_sq[slot][t] * invN - m * m;
            float a = gamma[t] * rsqrtf(v + BN_EPS);
            s_a[t] = a;
            s_b[t] = beta[t] - m * a;
        }
        __syncthreads();
    }
    int node = blockIdx.x * 8 + (t >> 5);           // grid 6250 * 8 warps = 50000
    const float4* src = FIRST ? (const float4*)xin : (const float4*)g_z3;
    float4 av, bv;
    if (!FIRST) { av = ((const float4*)s_a)[lane]; bv = ((const float4*)s_b)[lane]; }

    int beg = g_off[node], end = g_off[node + 1];
    float4 acc = src[node * 32 + lane];
    if (!FIRST) {
        acc.x = fmaxf(fmaf(acc.x, av.x, bv.x), 0.f);
        acc.y = fmaxf(fmaf(acc.y, av.y, bv.y), 0.f);
        acc.z = fmaxf(fmaf(acc.z, av.z, bv.z), 0.f);
        acc.w = fmaxf(fmaf(acc.w, av.w, bv.w), 0.f);
    }
    int j = beg;
    for (; j + 4 <= end; j += 4) {
        int n0 = g_csr_src[j],     n1 = g_csr_src[j + 1];
        int n2 = g_csr_src[j + 2], n3 = g_csr_src[j + 3];
        float4 v0 = src[n0 * 32 + lane];
        float4 v1 = src[n1 * 32 + lane];
        float4 v2 = src[n2 * 32 + lane];
        float4 v3 = src[n3 * 32 + lane];
        if (!FIRST) {
            v0.x = fmaxf(fmaf(v0.x, av.x, bv.x), 0.f); v0.y = fmaxf(fmaf(v0.y, av.y, bv.y), 0.f);
            v0.z = fmaxf(fmaf(v0.z, av.z, bv.z), 0.f); v0.w = fmaxf(fmaf(v0.w, av.w, bv.w), 0.f);
            v1.x = fmaxf(fmaf(v1.x, av.x, bv.x), 0.f); v1.y = fmaxf(fmaf(v1.y, av.y, bv.y), 0.f);
            v1.z = fmaxf(fmaf(v1.z, av.z, bv.z), 0.f); v1.w = fmaxf(fmaf(v1.w, av.w, bv.w), 0.f);
            v2.x = fmaxf(fmaf(v2.x, av.x, bv.x), 0.f); v2.y = fmaxf(fmaf(v2.y, av.y, bv.y), 0.f);
            v2.z = fmaxf(fmaf(v2.z, av.z, bv.z), 0.f); v2.w = fmaxf(fmaf(v2.w, av.w, bv.w), 0.f);
            v3.x = fmaxf(fmaf(v3.x, av.x, bv.x), 0.f); v3.y = fmaxf(fmaf(v3.y, av.y, bv.y), 0.f);
            v3.z = fmaxf(fmaf(v3.z, av.z, bv.z), 0.f); v3.w = fmaxf(fmaf(v3.w, av.w, bv.w), 0.f);
        }
        acc.x += v0.x + v1.x + v2.x + v3.x;
        acc.y += v0.y + v1.y + v2.y + v3.y;
        acc.z += v0.z + v1.z + v2.z + v3.z;
        acc.w += v0.w + v1.w + v2.w + v3.w;
    }
    for (; j < end; j++) {
        float4 v = src[g_csr_src[j] * 32 + lane];
        if (!FIRST) {
            v.x = fmaxf(fmaf(v.x, av.x, bv.x), 0.f);
            v.y = fmaxf(fmaf(v.y, av.y, bv.y), 0.f);
            v.z = fmaxf(fmaf(v.z, av.z, bv.z), 0.f);
            v.w = fmaxf(fmaf(v.w, av.w, bv.w), 0.f);
        }
        acc.x += v.x; acc.y += v.y; acc.z += v.z; acc.w += v.w;
    }
    uint2 hv = make_uint2(pack_hi(acc.x, acc.y), pack_hi(acc.z, acc.w));
    uint2 lv = make_uint2(pack_lo(acc.x, acc.y), pack_lo(acc.z, acc.w));
    ((uint2*)g_zh)[node * 32 + lane] = hv;
    ((uint2*)g_zl)[node * 32 + lane] = lv;
}

// ===================== persistent HMMA GEMM =====================
// Grid = GEMM_GRID persistent CTAs; each stages W once and loops over 64-row tiles.
// TRANS=false: A = g_zh/g_zl (pre-split bf16)            -> out=g_z2, stats slot=wslot
// TRANS=true : A = g_z2 with fused relu(BN1(x)) + split  -> out=g_z3, stats slot=wslot
#define LDA 272
#define SM_AH   0          /* 64*272  = 17408 */
#define SM_AL   17408
#define SM_WH   34816      /* 128*272 = 34816 */
#define SM_WL   69632
#define SM_BIAS 104448
#define SM_SUM  104960
#define SM_SQ   105472
#define SM_A1   105984
#define SM_B1   106496
#define SM_TOTAL 107008

template <bool TRANS>
__global__ __launch_bounds__(256, 2) void k_gemm_mma(int wslot, const float* __restrict__ bias,
                                                     const float* __restrict__ gamma,
                                                     const float* __restrict__ beta) {
    extern __shared__ __align__(16) char smem[];
    uint32_t sb = smem_u32(smem);
    int t = threadIdx.x, lane = t & 31, wid = t >> 5;
    int wm = wid & 1, wn = wid >> 1;           // 2 x 4 warp grid: 32-row x 32-col per warp
    float* out = TRANS ? g_z3 : g_z2;

    float* s_bias = (float*)(smem + SM_BIAS);
    float* s_sum  = (float*)(smem + SM_SUM);
    float* s_sq   = (float*)(smem + SM_SQ);
    float* s_a1   = (float*)(smem + SM_A1);
    float* s_b1   = (float*)(smem + SM_B1);
    if (t < 128) {
        s_bias[t] = bias[t]; s_sum[t] = 0.f; s_sq[t] = 0.f;
        if (TRANS) {
            const float invN = 1.f / (float)N_NODES;
            float m = g_stat_sum[wslot - 1][t] * invN;
            float v = g_stat_sq[wslot - 1][t] * invN - m * m;
            float a = gamma[t] * rsqrtf(v + BN_EPS);
            s_a1[t] = a;
            s_b1[t] = beta[t] - m * a;
        }
    }
    // ---- stage W (hi/lo) ONCE, padded rows ----
    {
        const float4* wh = (const float4*)(g_Wh + wslot * SLOT_W_BYTES);
        const float4* wl = (const float4*)(g_Wl + wslot * SLOT_W_BYTES);
        #pragma unroll
        for (int i = t; i < 2048; i += 256) {
            int row = i >> 4, c8 = i & 15;
            *(float4*)(smem + SM_WH + row * LDA + c8 * 16) = wh[i];
            *(float4*)(smem + SM_WL + row * LDA + c8 * 16) = wl[i];
        }
    }
    __syncthreads();

    // fragment addresses (tile-invariant)
    uint32_t aoffH = sb + SM_AH + (32 * wm + (lane & 15)) * LDA + (lane >> 4) * 16;
    uint32_t aoffL = aoffH + (SM_AL - SM_AH);
    int bg = lane >> 3;
    uint32_t boffH = sb + SM_WH + (32 * wn + (lane & 7) + ((bg >> 1) << 3)) * LDA + (bg & 1) * 16;
    uint32_t boffL = boffH + (SM_WL - SM_WH);

    for (int tile = blockIdx.x; tile < N_TILES; tile += GEMM_GRID) {
        int m0 = tile * 64;
        // ---- stage A tile (64 rows) ----
        if (TRANS) {
            #pragma unroll
            for (int i = t; i < 2048; i += 256) {
                int row = i >> 5, c4 = i & 31;
                float4 v = ((const float4*)g_z2)[(m0 + row) * 32 + c4];
                float4 al = ((const float4*)s_a1)[c4];
                float4 be = ((const float4*)s_b1)[c4];
                v.x = fmaxf(fmaf(v.x, al.x, be.x), 0.f);
                v.y = fmaxf(fmaf(v.y, al.y, be.y), 0.f);
                v.z = fmaxf(fmaf(v.z, al.z, be.z), 0.f);
                v.w = fmaxf(fmaf(v.w, al.w, be.w), 0.f);
                uint2 hv = make_uint2(pack_hi(v.x, v.y), pack_hi(v.z, v.w));
                uint2 lv = make_uint2(pack_lo(v.x, v.y), pack_lo(v.z, v.w));
                *(uint2*)(smem + SM_AH + row * LDA + c4 * 8) = hv;
                *(uint2*)(smem + SM_AL + row * LDA + c4 * 8) = lv;
            }
        } else {
            #pragma unroll
            for (int i = t; i < 1024; i += 256) {
                int row = i >> 4, c16 = i & 15;   // 16B chunks: 128 bf16 = 256B = 16 chunks
                float4 hv = ((const float4*)g_zh)[(m0 + row) * 16 + c16];
                float4 lv = ((const float4*)g_zl)[(m0 + row) * 16 + c16];
                *(float4*)(smem + SM_AH + row * LDA + c16 * 16) = hv;
                *(float4*)(smem + SM_AL + row * LDA + c16 * 16) = lv;
            }
        }
        __syncthreads();

        float acc[2][4][4];
        #pragma unroll
        for (int mt = 0; mt < 2; mt++)
            #pragma unroll
            for (int nt = 0; nt < 4; nt++)
                #pragma unroll
                for (int j = 0; j < 4; j++) acc[mt][nt][j] = 0.f;

        #pragma unroll
        for (int ks = 0; ks < 8; ks++) {
            uint32_t kb = ks * 32;
            uint32_t ah[2][4], al[2][4], bh[2][4], bl[2][4];
            #pragma unroll
            for (int mt = 0; mt < 2; mt++) {
                ldmx4(ah[mt], aoffH + mt * 16 * LDA + kb);
                ldmx4(al[mt], aoffL + mt * 16 * LDA + kb);
            }
            #pragma unroll
            for (int p = 0; p < 2; p++) {
                ldmx4(bh[p], boffH + p * 16 * LDA + kb);
                ldmx4(bl[p], boffL + p * 16 * LDA + kb);
            }
            #pragma unroll
            for (int mt = 0; mt < 2; mt++)
                #pragma unroll
                for (int nt = 0; nt < 4; nt++) {
                    const uint32_t* bfh = &bh[nt >> 1][(nt & 1) * 2];
                    const uint32_t* bfl = &bl[nt >> 1][(nt & 1) * 2];
                    mma_bf16(acc[mt][nt], ah[mt], bfh);   // Ah * Wh
                    mma_bf16(acc[mt][nt], al[mt], bfh);   // Al * Wh
                    mma_bf16(acc[mt][nt], ah[mt], bfl);   // Ah * Wl
                }
        }

        // ---- epilogue: bias, guarded store, BN stats into smem accumulators ----
        int colbase = 32 * wn + 2 * (lane & 3);
        int rowg    = m0 + 32 * wm + (lane >> 2);
        #pragma unroll
        for (int nt = 0; nt < 4; nt++) {
            int c = colbase + nt * 8;
            float b0 = s_bias[c], b1 = s_bias[c + 1];
            float s0 = 0.f, s1 = 0.f, q0 = 0.f, q1 = 0.f;
            #pragma unroll
            for (int mt = 0; mt < 2; mt++) {
                int r0 = rowg + mt * 16;
                int r1 = r0 + 8;
                float d0 = acc[mt][nt][0] + b0, d1 = acc[mt][nt][1] + b1;
                float d2 = acc[mt][nt][2] + b0, d3 = acc[mt][nt][3] + b1;
                if (r0 < N_NODES) {
                    *(float2*)(out + r0 * 128 + c) = make_float2(d0, d1);
                    s0 += d0; s1 += d1;
                    q0 = fmaf(d0, d0, q0); q1 = fmaf(d1, d1, q1);
                }
                if (r1 < N_NODES) {
                    *(float2*)(out + r1 * 128 + c) = make_float2(d2, d3);
                    s0 += d2; s1 += d3;
                    q0 = fmaf(d2, d2, q0); q1 = fmaf(d3, d3, q1);
                }
            }
            #pragma unroll
            for (int off = 4; off < 32; off <<= 1) {
                s0 += __shfl_xor_sync(0xffffffffu, s0, off);
                s1 += __shfl_xor_sync(0xffffffffu, s1, off);
                q0 += __shfl_xor_sync(0xffffffffu, q0, off);
                q1 += __shfl_xor_sync(0xffffffffu, q1, off);
            }
            if (lane < 4) {
                atomicAdd(&s_sum[c], s0);
                atomicAdd(&s_sum[c + 1], s1);
                atomicAdd(&s_sq[c], q0);
                atomicAdd(&s_sq[c + 1], q1);
            }
        }
        __syncthreads();   // epilogue done; A smem free for next tile
    }
    // flush accumulated stats once
    if (t < 128)  atomicAdd(&g_stat_sum[wslot][t], s_sum[t]);
    else          atomicAdd(&g_stat_sq[wslot][t - 128], s_sq[t - 128]);
}

// ===================== pooling (BN2+ReLU computed in-kernel), right after GEMM2 =====================
__global__ void k_pool(const float* __restrict__ gamma, const float* __restrict__ beta,
                       int slot, int layer) {
    int g = blockIdx.x, part = blockIdx.y, c = threadIdx.x;
    const float invN = 1.f / (float)N_NODES;
    float m = g_stat_sum[slot][c] * invN;
    float v = g_stat_sq[slot][c] * invN - m * m;
    float a = gamma[c] * rsqrtf(v + BN_EPS);
    float b = beta[c] - m * a;
    int beg = g_gstart[g], end = g_gstart[g + 1];
    int len = end - beg;
    int s = beg + (len * part) / 4;
    int e = beg + (len * (part + 1)) / 4;
    float acc = 0.f;
    for (int i = s; i < e; i++)
        acc += fmaxf(fmaf(g_z3[i * HIDDEN + c], a, b), 0.f);
    atomicAdd(&g_pooled[g * (N_LAYERS * HIDDEN) + layer * HIDDEN + c], acc);
}

// ===================== final MLP =====================
__global__ void k_fc(const float* __restrict__ fc1W, const float* __restrict__ fc1b,
                     const float* __restrict__ fc2W, const float* __restrict__ fc2b,
                     float* __restrict__ out) {
    __shared__ float p[N_LAYERS * HIDDEN];
    __shared__ float f1[HIDDEN];
    int g = blockIdx.x, t = threadIdx.x;
    for (int j = t; j < N_LAYERS * HIDDEN; j += HIDDEN)
        p[j] = g_pooled[g * (N_LAYERS * HIDDEN) + j];
    __syncthreads();
    float acc = fc1b[t];
    for (int k = 0; k < N_LAYERS * HIDDEN; k++)
        acc = fmaf(p[k], fc1W[k * HIDDEN + t], acc);
    f1[t] = fmaxf(acc, 0.f);
    __syncthreads();
    if (t < OUT_DIM) {
        float o = fc2b[t];
        for (int c = 0; c < HIDDEN; c++)
            o = fmaf(f1[c], fc2W[c * OUT_DIM + t], o);
        out[g * OUT_DIM + t] = o;
    }
}

// ===================== host launch =====================
extern "C" void kernel_launch(void* const* d_in, const int* in_sizes, int n_in,
                              void* d_out, int out_size) {
    const float* x        = (const float*)d_in[0];
    const float* conv_W1  = (const float*)d_in[1];
    const float* conv_b1  = (const float*)d_in[2];
    const float* mlp_bn_g = (const float*)d_in[3];
    const float* mlp_bn_b = (const float*)d_in[4];
    const float* conv_W2  = (const float*)d_in[5];
    const float* conv_b2  = (const float*)d_in[6];
    const float* out_bn_g = (const float*)d_in[7];
    const float* out_bn_b = (const float*)d_in[8];
    const float* fc1_W    = (const float*)d_in[9];
    const float* fc1_b    = (const float*)d_in[10];
    const float* fc2_W    = (const float*)d_in[11];
    const float* fc2_b    = (const float*)d_in[12];
    const int*   ei       = (const int*)  d_in[13];
    const int*   batch    = (const int*)  d_in[14];
    float* out = (float*)d_out;

    cudaFuncSetAttribute((const void*)k_gemm_mma<false>,
                         cudaFuncAttributeMaxDynamicSharedMemorySize, SM_TOTAL);
    cudaFuncSetAttribute((const void*)k_gemm_mma<true>,
                         cudaFuncAttributeMaxDynamicSharedMemorySize, SM_TOTAL);

    k_zero<<<(N_GRAPHS * N_LAYERS * HIDDEN + 255) / 256, 256>>>();
    k_hist<<<(N_EDGES + 255) / 256, 256>>>(ei);
    k_scan1<<<196, 256>>>();
    k_scan23g<<<196, 256>>>(batch);
    k_scatter<<<(N_EDGES + 255) / 256, 256>>>(ei);
    k_convW<<<10, 256>>>(conv_W1, conv_W2);

    const int AB = N_NODES / 8;   // 6250 (exact)
    for (int i = 0; i < N_LAYERS; i++) {
        if (i == 0)
            k_agg<true><<<AB, 256>>>(x, nullptr, nullptr, 0);
        else
            k_agg<false><<<AB, 256>>>(nullptr, out_bn_g + (i - 1) * HIDDEN,
                                      out_bn_b + (i - 1) * HIDDEN, 2 * (i - 1) + 1);
        k_gemm_mma<false><<<GEMM_GRID, 256, SM_TOTAL>>>(2 * i, conv_b1 + i * HIDDEN,
                                                        nullptr, nullptr);
        k_gemm_mma<true><<<GEMM_GRID, 256, SM_TOTAL>>>(2 * i + 1, conv_b2 + i * HIDDEN,
                                                       mlp_bn_g + i * HIDDEN,
                                                       mlp_bn_b + i * HIDDEN);
        k_pool<<<dim3(N_GRAPHS, 4), HIDDEN>>>(out_bn_g + i * HIDDEN, out_bn_b + i * HIDDEN,
                                              2 * i + 1, i);
    }
    k_fc<<<N_GRAPHS, HIDDEN>>>(fc1_W, fc1_b, fc2_W, fc2_b, out);
}